// round 5
// baseline (speedup 1.0000x reference)
#include <cuda_runtime.h>

#define TN 2048
#define RMAXF 8.0f
#define MAXE 640000
#define MAXAB 32768

// Radial table: g_table[i][t*16+m] = (silu(rb(r_i)@w1[t]) @ w2[t])[m] / sqrt(20)
// g(r)==0 exactly for r >~ 6.5 (gaussians vanish, silu(0)=0) so clamping
// r>RMAXF into the zero tail is exact.
__device__ float g_table[TN * 48];
__device__ float rb_tab[TN * 10];
__device__ float act_tab[TN * 300];
// rw[t*AB + a] = dot(atom_rep[t][a][:], w_out)
__device__ float rw_table[3 * MAXAB];
// counting sort by src atom
__device__ float4 rec[MAXE];          // (c0,c1,c2, dst) sorted by src atom
__device__ int hist[MAXAB];
__device__ int binstart[MAXAB + 1];
__device__ int cursor[MAXAB];

// ---------------- table build: 3 flat, embarrassingly parallel kernels ----
__global__ void rb_kernel()
{
    int id = blockIdx.x * blockDim.x + threadIdx.x;
    if (id >= TN * 10) return;
    int i = id / 10, k = id % 10;
    float r = (float)i * (RMAXF / (float)(TN - 1));
    const float step = 4.0f / 9.0f;
    float d = (r - (float)k * step) / step;
    rb_tab[id] = expf(-d * d) * 1.12f;
}

__global__ void act_kernel(const float* __restrict__ w1)
{
    int id = blockIdx.x * blockDim.x + threadIdx.x;
    if (id >= TN * 300) return;
    int i = id / 300, rem = id % 300;
    int t = rem / 100, j = rem % 100;
    const float* RB = rb_tab + i * 10;
    const float* W1 = w1 + t * 1000 + j;  // stride 100 over k
    float a = 0.f;
#pragma unroll
    for (int k = 0; k < 10; k++)
        a = fmaf(__ldg(RB + k), __ldg(W1 + k * 100), a);
    act_tab[id] = a / (1.f + expf(-a));
}

__global__ void gtab_kernel(const float* __restrict__ w2)
{
    int id = blockIdx.x * blockDim.x + threadIdx.x;
    if (id >= TN * 48) return;
    int i = id / 48, o = id % 48;
    int t = o >> 4, m = o & 15;
    const float* A = act_tab + i * 300 + t * 100;
    const float* W = w2 + t * 1600 + m;   // stride 16 over j
    float h0 = 0.f, h1 = 0.f;
#pragma unroll 4
    for (int j = 0; j < 100; j += 2) {
        h0 = fmaf(__ldg(A + j),     __ldg(W + j * 16),       h0);
        h1 = fmaf(__ldg(A + j + 1), __ldg(W + (j + 1) * 16), h1);
    }
    g_table[id] = (h0 + h1) * 0.22360679774997896f;  // 1/sqrt(20)
}

// ---------------- rw: warp per row -----------------------------------------
__global__ void rw_kernel(const float* __restrict__ atom_rep,
                          const float* __restrict__ w_out, int rows)
{
    int g = blockIdx.x * blockDim.x + threadIdx.x;
    int row = g >> 5;
    int lane = g & 31;
    if (row >= rows) return;
    float4 a = __ldg((const float4*)atom_rep + (size_t)row * 32 + lane);
    float4 wv = __ldg((const float4*)w_out + lane);
    float s = fmaf(a.x, wv.x, fmaf(a.y, wv.y, fmaf(a.z, wv.z, a.w * wv.w)));
#pragma unroll
    for (int off = 16; off > 0; off >>= 1)
        s += __shfl_xor_sync(0xFFFFFFFFu, s, off);
    if (lane == 0) rw_table[row] = s;
}

// ---------------- counting sort by src atom ---------------------------------
__global__ void zero_hist_kernel(int nbins)
{
    int i = blockIdx.x * blockDim.x + threadIdx.x;
    if (i < nbins) hist[i] = 0;
}

__global__ void hist_kernel(const int* __restrict__ edges, int E,
                            int n_edges_b, int n_atoms)
{
    int e = blockIdx.x * blockDim.x + threadIdx.x;
    if (e >= E) return;
    int b = e / n_edges_b;
    int2 se = ((const int2*)edges)[e];
    atomicAdd(&hist[b * n_atoms + se.x], 1);
}

// single-block inclusive scan over nbins (<= a few chunks of 1024)
__global__ void __launch_bounds__(1024) scan_kernel(int nbins)
{
    __shared__ int s_w[32];
    __shared__ int s_carry;
    int tid = threadIdx.x, lane = tid & 31, w = tid >> 5;
    if (tid == 0) s_carry = 0;
    __syncthreads();
    for (int base = 0; base < nbins; base += 1024) {
        int i = base + tid;
        int v = (i < nbins) ? hist[i] : 0;
        int x = v;
#pragma unroll
        for (int o = 1; o < 32; o <<= 1) {
            int y = __shfl_up_sync(0xFFFFFFFFu, x, o);
            if (lane >= o) x += y;
        }
        if (lane == 31) s_w[w] = x;
        __syncthreads();
        if (w == 0) {
            int y = s_w[lane];
#pragma unroll
            for (int o = 1; o < 32; o <<= 1) {
                int z = __shfl_up_sync(0xFFFFFFFFu, y, o);
                if (lane >= o) y += z;
            }
            s_w[lane] = y;
        }
        __syncthreads();
        int incl = x + (w > 0 ? s_w[w - 1] : 0) + s_carry;
        if (i < nbins) {
            binstart[i] = incl - v;
            cursor[i]   = incl - v;
        }
        __syncthreads();
        if (tid == 1023) s_carry = incl;
        __syncthreads();
    }
    if (tid == 0) binstart[nbins] = s_carry;
}

// ---------------- phase A: per-edge scalars + sorted placement --------------
__global__ void __launch_bounds__(256) phaseA_kernel(
    const float* __restrict__ atom_xyz,
    const float* __restrict__ probe_xyz,
    const int*   __restrict__ edges,
    const float* __restrict__ ped,
    const float* __restrict__ cell,
    int E, int n_edges_b, int n_atoms, int n_probes)
{
    __shared__ float s_sh[256 * 17];   // sh[16] per edge, pitch 17
    __shared__ int   s_i0[256];
    __shared__ float s_w[256];
    __shared__ int   s_src[256];
    __shared__ int   s_dst[256];
    __shared__ float s_sc[256 * 4];

    int tid = threadIdx.x;
    int e = blockIdx.x * 256 + tid;

    if (e < E) {
        int b = e / n_edges_b;
        int2 se = ((const int2*)edges)[e];
        int src_g = b * n_atoms + se.x;
        int dst_g = b * n_probes + se.y;
        float px = ped[3 * e], py = ped[3 * e + 1], pz = ped[3 * e + 2];
        const float* C = cell + b * 9;
        float dx = fmaf(px, __ldg(C + 0), fmaf(py, __ldg(C + 3), pz * __ldg(C + 6)));
        float dy = fmaf(px, __ldg(C + 1), fmaf(py, __ldg(C + 4), pz * __ldg(C + 7)));
        float dz = fmaf(px, __ldg(C + 2), fmaf(py, __ldg(C + 5), pz * __ldg(C + 8)));
        float vx = probe_xyz[3 * dst_g + 0] - atom_xyz[3 * src_g + 0] - dx;
        float vy = probe_xyz[3 * dst_g + 1] - atom_xyz[3 * src_g + 1] - dy;
        float vz = probe_xyz[3 * dst_g + 2] - atom_xyz[3 * src_g + 2] - dz;
        float r2 = fmaf(vx, vx, fmaf(vy, vy, vz * vz));
        float r = sqrtf(r2);
        float rinv = 1.0f / fmaxf(r, 1e-9f);
        float x = vx * rinv, y = vy * rinv, z = vz * rinv;
        float x2 = x * x, y2 = y * y, z2 = z * z;

        const float s3  = 1.7320508075688772f;
        const float s15 = 3.872983346207417f;
        float* S = s_sh + tid * 17;
        S[0]  = 1.f;
        S[1]  = s3 * x;
        S[2]  = s3 * y;
        S[3]  = s3 * z;
        S[4]  = s15 * x * y;
        S[5]  = s15 * y * z;
        S[6]  = 1.118033988749895f * (3.f * z2 - 1.f);
        S[7]  = s15 * x * z;
        S[8]  = 1.9364916731037085f * (x2 - y2);
        S[9]  = 2.091650066335189f * y * (3.f * x2 - y2);
        S[10] = 10.246950765959598f * x * y * z;
        S[11] = 1.6201851746019651f * y * (5.f * z2 - 1.f);
        S[12] = 1.3228756555322954f * (5.f * z2 * z - 3.f * z);
        S[13] = 1.6201851746019651f * x * (5.f * z2 - 1.f);
        S[14] = 5.123475382979799f * z * (x2 - y2);
        S[15] = 2.091650066335189f * x * (x2 - 3.f * y2);

        float f = r * ((float)(TN - 1) / RMAXF);
        f = fminf(f, (float)(TN - 1));
        int i0 = (int)f;
        i0 = min(i0, TN - 2);
        s_i0[tid] = i0;
        s_w[tid] = f - (float)i0;
        s_src[tid] = src_g;
        s_dst[tid] = dst_g;
    } else {
        float* S = s_sh + tid * 17;
#pragma unroll
        for (int m = 0; m < 16; m++) S[m] = 0.f;
        s_i0[tid] = 0;
        s_w[tid] = 0.f;
        s_src[tid] = 0;
        s_dst[tid] = -1;
    }
    __syncthreads();

    // half-warp per edge: coalesced table read + 16-lane reduce
    {
        int lane = tid & 31;
        int m = lane & 15;
        int hw = (tid >> 5) * 2 + (lane >> 4);
#pragma unroll 2
        for (int k = 0; k < 16; k++) {
            int el = hw * 16 + k;
            int i0 = s_i0[el];
            float w = s_w[el];
            float shm = s_sh[el * 17 + m];
            const float* G = g_table + i0 * 48 + m;
#pragma unroll
            for (int t = 0; t < 3; t++) {
                float g0 = __ldg(G + t * 16);
                float g1 = __ldg(G + 48 + t * 16);
                float v = shm * fmaf(w, g1 - g0, g0);
                v += __shfl_xor_sync(0xFFFFFFFFu, v, 1);
                v += __shfl_xor_sync(0xFFFFFFFFu, v, 2);
                v += __shfl_xor_sync(0xFFFFFFFFu, v, 4);
                v += __shfl_xor_sync(0xFFFFFFFFu, v, 8);
                if (m == 0) s_sc[el * 4 + t] = v;
            }
        }
    }
    __syncthreads();

    // place record into src-sorted slot
    if (e < E) {
        int slot = atomicAdd(&cursor[s_src[tid]], 1);
        rec[slot] = make_float4(s_sc[tid * 4 + 0], s_sc[tid * 4 + 1],
                                s_sc[tid * 4 + 2],
                                __int_as_float(s_dst[tid]));
    }
}

// ---------------- phase B: warp per atom, rep in registers ------------------
__global__ void __launch_bounds__(256) phaseB_kernel(
    const float* __restrict__ atom_rep,
    float* __restrict__ probes,
    float* __restrict__ out,
    int AB)
{
    int g = blockIdx.x * blockDim.x + threadIdx.x;
    int a = g >> 5;
    int lane = g & 31;
    if (a >= AB) return;

    const float4* rep4 = (const float4*)atom_rep;
    float4 r0 = __ldg(rep4 + (size_t)a * 32 + lane);
    float4 r1 = __ldg(rep4 + (size_t)(AB + a) * 32 + lane);
    float4 r2 = __ldg(rep4 + (size_t)(2 * AB + a) * 32 + lane);
    float w0 = rw_table[a];
    float w1 = rw_table[AB + a];
    float w2 = rw_table[2 * AB + a];

    int s   = binstart[a];
    int end = binstart[a + 1];
    for (; s < end; s++) {
        float4 c = __ldg(&rec[s]);   // same addr all lanes -> broadcast
        int dst = __float_as_int(c.w);
        float4 m;
        m.x = fmaf(c.x, r0.x, fmaf(c.y, r1.x, c.z * r2.x));
        m.y = fmaf(c.x, r0.y, fmaf(c.y, r1.y, c.z * r2.y));
        m.z = fmaf(c.x, r0.z, fmaf(c.y, r1.z, c.z * r2.z));
        m.w = fmaf(c.x, r0.w, fmaf(c.y, r1.w, c.z * r2.w));
        float* dptr = probes + (size_t)dst * 128 + lane * 4;
        asm volatile("red.global.add.v4.f32 [%0], {%1, %2, %3, %4};"
                     :: "l"(dptr), "f"(m.x), "f"(m.y), "f"(m.z), "f"(m.w)
                     : "memory");
        if (lane == 0) {
            float ov = fmaf(c.x, w0, fmaf(c.y, w1, c.z * w2));
            atomicAdd(out + dst, ov);
        }
    }
}

extern "C" void kernel_launch(void* const* d_in, const int* in_sizes, int n_in,
                              void* d_out, int out_size)
{
    const float* atom_xyz  = (const float*)d_in[0];
    const float* probe_xyz = (const float*)d_in[1];
    const int*   edges     = (const int*)d_in[2];
    const float* ped       = (const float*)d_in[3];
    const float* cell      = (const float*)d_in[4];
    const float* atom_rep  = (const float*)d_in[8];
    const float* w1        = (const float*)d_in[9];
    const float* w2        = (const float*)d_in[10];
    const float* w_out     = (const float*)d_in[11];

    int B         = in_sizes[4] / 9;
    int n_atoms   = in_sizes[0] / (3 * B);
    int n_probes  = in_sizes[1] / (3 * B);
    int n_edges_b = in_sizes[2] / (2 * B);
    int E  = B * n_edges_b;
    int AB = B * n_atoms;
    int P  = B * n_probes;

    float* out    = (float*)d_out;      // first P: (B,P) potential
    float* probes = out + P;            // next P*128: probe features

    cudaMemsetAsync(d_out, 0, (size_t)(P + (size_t)P * 128) * sizeof(float), 0);

    // table build (flat parallel)
    rb_kernel<<<(TN * 10 + 255) / 256, 256>>>();
    act_kernel<<<(TN * 300 + 255) / 256, 256>>>(w1);
    gtab_kernel<<<(TN * 48 + 255) / 256, 256>>>(w2);
    rw_kernel<<<(3 * AB * 32 + 255) / 256, 256>>>(atom_rep, w_out, 3 * AB);

    // counting sort setup
    zero_hist_kernel<<<(AB + 255) / 256, 256>>>(AB);
    hist_kernel<<<(E + 255) / 256, 256>>>(edges, E, n_edges_b, n_atoms);
    scan_kernel<<<1, 1024>>>(AB);

    // per-edge scalars + sorted placement
    phaseA_kernel<<<(E + 255) / 256, 256>>>(atom_xyz, probe_xyz, edges, ped,
                                            cell, E, n_edges_b, n_atoms,
                                            n_probes);
    // atom-major accumulate + scatter
    phaseB_kernel<<<(AB * 32 + 255) / 256, 256>>>(atom_rep, probes, out, AB);
}

// round 6
// speedup vs baseline: 1.2674x; 1.2674x over previous
#include <cuda_runtime.h>

#define TN 2048
#define RMAXF 8.0f
#define MAXAB 32768

// Radial table: g_table[i][t*16+m] = (silu(rb(r_i)@w1[t]) @ w2[t])[m] / sqrt(20)
// g(r)==0 exactly for r >~ 6.5 (gaussians vanish, silu(0)=0) so clamping
// r>RMAXF into the zero tail is exact.
__device__ float g_table[TN * 48];
__device__ float rb_tab[TN * 10];
__device__ float act_tab[TN * 300];
// rw[t*AB + a] = dot(atom_rep[t][a][:], w_out)
__device__ float rw_table[3 * MAXAB];

// ---------------- table build: 3 flat, embarrassingly parallel kernels ----
__global__ void rb_kernel()
{
    int id = blockIdx.x * blockDim.x + threadIdx.x;
    if (id >= TN * 10) return;
    int i = id / 10, k = id % 10;
    float r = (float)i * (RMAXF / (float)(TN - 1));
    const float step = 4.0f / 9.0f;
    float d = (r - (float)k * step) / step;
    rb_tab[id] = expf(-d * d) * 1.12f;
}

__global__ void act_kernel(const float* __restrict__ w1)
{
    int id = blockIdx.x * blockDim.x + threadIdx.x;
    if (id >= TN * 300) return;
    int i = id / 300, rem = id % 300;
    int t = rem / 100, j = rem % 100;
    const float* RB = rb_tab + i * 10;
    const float* W1 = w1 + t * 1000 + j;  // stride 100 over k
    float a = 0.f;
#pragma unroll
    for (int k = 0; k < 10; k++)
        a = fmaf(__ldg(RB + k), __ldg(W1 + k * 100), a);
    act_tab[id] = a / (1.f + expf(-a));
}

__global__ void gtab_kernel(const float* __restrict__ w2)
{
    int id = blockIdx.x * blockDim.x + threadIdx.x;
    if (id >= TN * 48) return;
    int i = id / 48, o = id % 48;
    int t = o >> 4, m = o & 15;
    const float* A = act_tab + i * 300 + t * 100;
    const float* W = w2 + t * 1600 + m;   // stride 16 over j
    float h0 = 0.f, h1 = 0.f;
#pragma unroll 4
    for (int j = 0; j < 100; j += 2) {
        h0 = fmaf(__ldg(A + j),     __ldg(W + j * 16),       h0);
        h1 = fmaf(__ldg(A + j + 1), __ldg(W + (j + 1) * 16), h1);
    }
    g_table[id] = (h0 + h1) * 0.22360679774997896f;  // 1/sqrt(20)
}

// ---------------- rw: warp per row -----------------------------------------
__global__ void rw_kernel(const float* __restrict__ atom_rep,
                          const float* __restrict__ w_out, int rows)
{
    int g = blockIdx.x * blockDim.x + threadIdx.x;
    int row = g >> 5;
    int lane = g & 31;
    if (row >= rows) return;
    float4 a = __ldg((const float4*)atom_rep + (size_t)row * 32 + lane);
    float4 wv = __ldg((const float4*)w_out + lane);
    float s = fmaf(a.x, wv.x, fmaf(a.y, wv.y, fmaf(a.z, wv.z, a.w * wv.w)));
#pragma unroll
    for (int off = 16; off > 0; off >>= 1)
        s += __shfl_xor_sync(0xFFFFFFFFu, s, off);
    if (lane == 0) rw_table[row] = s;
}

// ---------------- fused edge kernel ------------------------------------------
__global__ void __launch_bounds__(256) edge_kernel(
    const float* __restrict__ atom_xyz,
    const float* __restrict__ probe_xyz,
    const int*   __restrict__ edges,
    const float* __restrict__ ped,
    const float* __restrict__ cell,
    const float* __restrict__ atom_rep,
    float* __restrict__ probes,
    float* __restrict__ out,
    int E, int n_edges_b, int n_atoms, int n_probes, int AB)
{
    __shared__ float s_sh[256 * 17];   // sh[16] per edge, pitch 17 (bank-safe)
    __shared__ int   s_i0[256];
    __shared__ float s_w[256];
    __shared__ int   s_src[256];
    __shared__ int   s_dst[256];
    __shared__ float s_sc[256 * 4];    // 3 scalars per edge, pitch 4

    int tid = threadIdx.x;
    int e = blockIdx.x * 256 + tid;

    // ---- Phase 1: thread = edge; geometry + SH + table index ----
    if (e < E) {
        int b = e / n_edges_b;
        int2 se = ((const int2*)edges)[e];
        int src_g = b * n_atoms + se.x;
        int dst_g = b * n_probes + se.y;
        float px = ped[3 * e], py = ped[3 * e + 1], pz = ped[3 * e + 2];
        const float* C = cell + b * 9;
        float dx = fmaf(px, __ldg(C + 0), fmaf(py, __ldg(C + 3), pz * __ldg(C + 6)));
        float dy = fmaf(px, __ldg(C + 1), fmaf(py, __ldg(C + 4), pz * __ldg(C + 7)));
        float dz = fmaf(px, __ldg(C + 2), fmaf(py, __ldg(C + 5), pz * __ldg(C + 8)));
        float vx = probe_xyz[3 * dst_g + 0] - atom_xyz[3 * src_g + 0] - dx;
        float vy = probe_xyz[3 * dst_g + 1] - atom_xyz[3 * src_g + 1] - dy;
        float vz = probe_xyz[3 * dst_g + 2] - atom_xyz[3 * src_g + 2] - dz;
        float r2 = fmaf(vx, vx, fmaf(vy, vy, vz * vz));
        float r = sqrtf(r2);
        float rinv = 1.0f / fmaxf(r, 1e-9f);
        float x = vx * rinv, y = vy * rinv, z = vz * rinv;
        float x2 = x * x, y2 = y * y, z2 = z * z;

        const float s3  = 1.7320508075688772f;
        const float s15 = 3.872983346207417f;
        float* S = s_sh + tid * 17;
        S[0]  = 1.f;
        S[1]  = s3 * x;
        S[2]  = s3 * y;
        S[3]  = s3 * z;
        S[4]  = s15 * x * y;
        S[5]  = s15 * y * z;
        S[6]  = 1.118033988749895f * (3.f * z2 - 1.f);
        S[7]  = s15 * x * z;
        S[8]  = 1.9364916731037085f * (x2 - y2);
        S[9]  = 2.091650066335189f * y * (3.f * x2 - y2);
        S[10] = 10.246950765959598f * x * y * z;
        S[11] = 1.6201851746019651f * y * (5.f * z2 - 1.f);
        S[12] = 1.3228756555322954f * (5.f * z2 * z - 3.f * z);
        S[13] = 1.6201851746019651f * x * (5.f * z2 - 1.f);
        S[14] = 5.123475382979799f * z * (x2 - y2);
        S[15] = 2.091650066335189f * x * (x2 - 3.f * y2);

        float f = r * ((float)(TN - 1) / RMAXF);
        f = fminf(f, (float)(TN - 1));
        int i0 = (int)f;
        i0 = min(i0, TN - 2);
        s_i0[tid] = i0;
        s_w[tid] = f - (float)i0;
        s_src[tid] = src_g;
        s_dst[tid] = dst_g;
    } else {
        float* S = s_sh + tid * 17;
#pragma unroll
        for (int m = 0; m < 16; m++) S[m] = 0.f;
        s_i0[tid] = 0;
        s_w[tid] = 0.f;
        s_src[tid] = 0;
        s_dst[tid] = -1;
    }
    __syncthreads();

    // ---- Phase 1.5: half-warp = edge; coalesced table read + reduce ----
    {
        int lane = tid & 31;
        int m = lane & 15;
        int hw = (tid >> 5) * 2 + (lane >> 4);  // half-warp id 0..15
#pragma unroll 2
        for (int k = 0; k < 16; k++) {
            int el = hw * 16 + k;
            int i0 = s_i0[el];
            float w = s_w[el];
            float shm = s_sh[el * 17 + m];
            const float* G = g_table + i0 * 48 + m;
#pragma unroll
            for (int t = 0; t < 3; t++) {
                float g0 = __ldg(G + t * 16);
                float g1 = __ldg(G + 48 + t * 16);
                float v = shm * fmaf(w, g1 - g0, g0);
                v += __shfl_xor_sync(0xFFFFFFFFu, v, 1);
                v += __shfl_xor_sync(0xFFFFFFFFu, v, 2);
                v += __shfl_xor_sync(0xFFFFFFFFu, v, 4);
                v += __shfl_xor_sync(0xFFFFFFFFu, v, 8);
                if (m == 0) s_sc[el * 4 + t] = v;
            }
        }
    }
    __syncthreads();

    // ---- Phase 2: warp = edge; coalesced gather + vector red scatter ----
    int lane = tid & 31;
    int base = (tid >> 5) * 32;
    const float4* rep4 = (const float4*)atom_rep;  // [t][AB][32 float4]
    size_t repT = (size_t)AB * 32;
#pragma unroll 4
    for (int k = 0; k < 32; k++) {
        int el = base + k;
        int dst = s_dst[el];
        if (dst < 0) continue;  // warp-uniform (only in last block)
        float c0 = s_sc[el * 4 + 0];
        float c1 = s_sc[el * 4 + 1];
        float c2 = s_sc[el * 4 + 2];
        int src = s_src[el];
        const float4* p0 = rep4 + (size_t)src * 32 + lane;
        float4 a0 = __ldg(p0);
        float4 a1 = __ldg(p0 + repT);
        float4 a2 = __ldg(p0 + 2 * repT);
        float4 m;
        m.x = fmaf(c0, a0.x, fmaf(c1, a1.x, c2 * a2.x));
        m.y = fmaf(c0, a0.y, fmaf(c1, a1.y, c2 * a2.y));
        m.z = fmaf(c0, a0.z, fmaf(c1, a1.z, c2 * a2.z));
        m.w = fmaf(c0, a0.w, fmaf(c1, a1.w, c2 * a2.w));
        float* dptr = probes + (size_t)dst * 128 + lane * 4;
        asm volatile("red.global.add.v4.f32 [%0], {%1, %2, %3, %4};"
                     :: "l"(dptr), "f"(m.x), "f"(m.y), "f"(m.z), "f"(m.w)
                     : "memory");
        if (lane == 0) {
            float ov = fmaf(c0, rw_table[src],
                       fmaf(c1, rw_table[AB + src],
                            c2 * rw_table[2 * AB + src]));
            atomicAdd(out + dst, ov);
        }
    }
}

extern "C" void kernel_launch(void* const* d_in, const int* in_sizes, int n_in,
                              void* d_out, int out_size)
{
    const float* atom_xyz  = (const float*)d_in[0];
    const float* probe_xyz = (const float*)d_in[1];
    const int*   edges     = (const int*)d_in[2];
    const float* ped       = (const float*)d_in[3];
    const float* cell      = (const float*)d_in[4];
    const float* atom_rep  = (const float*)d_in[8];
    const float* w1        = (const float*)d_in[9];
    const float* w2        = (const float*)d_in[10];
    const float* w_out     = (const float*)d_in[11];

    int B         = in_sizes[4] / 9;
    int n_atoms   = in_sizes[0] / (3 * B);
    int n_probes  = in_sizes[1] / (3 * B);
    int n_edges_b = in_sizes[2] / (2 * B);
    int E  = B * n_edges_b;
    int AB = B * n_atoms;
    int P  = B * n_probes;

    float* out    = (float*)d_out;      // first P: (B,P) potential
    float* probes = out + P;            // next P*128: probe features

    cudaMemsetAsync(d_out, 0, (size_t)(P + (size_t)P * 128) * sizeof(float), 0);

    // table build (flat parallel) + rw precompute
    rb_kernel<<<(TN * 10 + 255) / 256, 256>>>();
    act_kernel<<<(TN * 300 + 255) / 256, 256>>>(w1);
    gtab_kernel<<<(TN * 48 + 255) / 256, 256>>>(w2);
    rw_kernel<<<(3 * AB * 32 + 255) / 256, 256>>>(atom_rep, w_out, 3 * AB);

    edge_kernel<<<(E + 255) / 256, 256>>>(atom_xyz, probe_xyz, edges, ped, cell,
                                          atom_rep, probes, out,
                                          E, n_edges_b, n_atoms, n_probes, AB);
}

// round 7
// speedup vs baseline: 1.3642x; 1.0764x over previous
#include <cuda_runtime.h>
#include <cuda_fp16.h>

#define TN 2048
#define RMAXF 8.0f
#define MAXAB 32768

// Radial table: g_table[i][t*16+m] = (silu(rb(r_i)@w1[t]) @ w2[t])[m] / sqrt(20)
// g(r)==0 exactly for r >~ 6.5 (gaussians vanish, silu(0)=0) so clamping
// r>RMAXF into the zero tail is exact.
__device__ float g_table[TN * 48];
__device__ float rb_tab[TN * 10];
__device__ float act_tab[TN * 300];
// rw[t*AB + a] = dot(atom_rep[t][a][:], w_out)
__device__ float rw_table[3 * MAXAB];
// fp16 copy of atom_rep (halves gather traffic; accumulation stays fp32)
__device__ __half rep16[3 * MAXAB * 128];

// ---------------- table build: 3 flat, embarrassingly parallel kernels ----
__global__ void rb_kernel()
{
    int id = blockIdx.x * blockDim.x + threadIdx.x;
    if (id >= TN * 10) return;
    int i = id / 10, k = id % 10;
    float r = (float)i * (RMAXF / (float)(TN - 1));
    const float step = 4.0f / 9.0f;
    float d = (r - (float)k * step) / step;
    rb_tab[id] = expf(-d * d) * 1.12f;
}

__global__ void act_kernel(const float* __restrict__ w1)
{
    int id = blockIdx.x * blockDim.x + threadIdx.x;
    if (id >= TN * 300) return;
    int i = id / 300, rem = id % 300;
    int t = rem / 100, j = rem % 100;
    const float* RB = rb_tab + i * 10;
    const float* W1 = w1 + t * 1000 + j;  // stride 100 over k
    float a = 0.f;
#pragma unroll
    for (int k = 0; k < 10; k++)
        a = fmaf(__ldg(RB + k), __ldg(W1 + k * 100), a);
    act_tab[id] = a / (1.f + expf(-a));
}

__global__ void gtab_kernel(const float* __restrict__ w2)
{
    int id = blockIdx.x * blockDim.x + threadIdx.x;
    if (id >= TN * 48) return;
    int i = id / 48, o = id % 48;
    int t = o >> 4, m = o & 15;
    const float* A = act_tab + i * 300 + t * 100;
    const float* W = w2 + t * 1600 + m;   // stride 16 over j
    float h0 = 0.f, h1 = 0.f;
#pragma unroll 4
    for (int j = 0; j < 100; j += 2) {
        h0 = fmaf(__ldg(A + j),     __ldg(W + j * 16),       h0);
        h1 = fmaf(__ldg(A + j + 1), __ldg(W + (j + 1) * 16), h1);
    }
    g_table[id] = (h0 + h1) * 0.22360679774997896f;  // 1/sqrt(20)
}

// ---------------- rep16 conversion: half2 per thread ------------------------
__global__ void rep16_kernel(const float* __restrict__ atom_rep, int n2)
{
    int id = blockIdx.x * blockDim.x + threadIdx.x;
    if (id >= n2) return;
    float2 f = __ldg((const float2*)atom_rep + id);
    ((__half2*)rep16)[id] = __floats2half2_rn(f.x, f.y);
}

// ---------------- rw: warp per row -----------------------------------------
__global__ void rw_kernel(const float* __restrict__ atom_rep,
                          const float* __restrict__ w_out, int rows)
{
    int g = blockIdx.x * blockDim.x + threadIdx.x;
    int row = g >> 5;
    int lane = g & 31;
    if (row >= rows) return;
    float4 a = __ldg((const float4*)atom_rep + (size_t)row * 32 + lane);
    float4 wv = __ldg((const float4*)w_out + lane);
    float s = fmaf(a.x, wv.x, fmaf(a.y, wv.y, fmaf(a.z, wv.z, a.w * wv.w)));
#pragma unroll
    for (int off = 16; off > 0; off >>= 1)
        s += __shfl_xor_sync(0xFFFFFFFFu, s, off);
    if (lane == 0) rw_table[row] = s;
}

// ---------------- fused edge kernel ------------------------------------------
__global__ void __launch_bounds__(256) edge_kernel(
    const float* __restrict__ atom_xyz,
    const float* __restrict__ probe_xyz,
    const int*   __restrict__ edges,
    const float* __restrict__ ped,
    const float* __restrict__ cell,
    float* __restrict__ probes,
    float* __restrict__ out,
    int E, int n_edges_b, int n_atoms, int n_probes, int AB)
{
    __shared__ float s_sh[256 * 17];   // sh[16] per edge, pitch 17 (bank-safe)
    __shared__ int   s_i0[256];
    __shared__ float s_w[256];
    __shared__ int   s_src[256];
    __shared__ int   s_dst[256];
    __shared__ float s_sc[256 * 4];    // 3 scalars per edge, pitch 4

    int tid = threadIdx.x;
    int e = blockIdx.x * 256 + tid;

    // ---- Phase 1: thread = edge; geometry + SH + table index ----
    if (e < E) {
        int b = e / n_edges_b;
        int2 se = ((const int2*)edges)[e];
        int src_g = b * n_atoms + se.x;
        int dst_g = b * n_probes + se.y;
        float px = ped[3 * e], py = ped[3 * e + 1], pz = ped[3 * e + 2];
        const float* C = cell + b * 9;
        float dx = fmaf(px, __ldg(C + 0), fmaf(py, __ldg(C + 3), pz * __ldg(C + 6)));
        float dy = fmaf(px, __ldg(C + 1), fmaf(py, __ldg(C + 4), pz * __ldg(C + 7)));
        float dz = fmaf(px, __ldg(C + 2), fmaf(py, __ldg(C + 5), pz * __ldg(C + 8)));
        float vx = probe_xyz[3 * dst_g + 0] - atom_xyz[3 * src_g + 0] - dx;
        float vy = probe_xyz[3 * dst_g + 1] - atom_xyz[3 * src_g + 1] - dy;
        float vz = probe_xyz[3 * dst_g + 2] - atom_xyz[3 * src_g + 2] - dz;
        float r2 = fmaf(vx, vx, fmaf(vy, vy, vz * vz));
        float r = sqrtf(r2);
        float rinv = 1.0f / fmaxf(r, 1e-9f);
        float x = vx * rinv, y = vy * rinv, z = vz * rinv;
        float x2 = x * x, y2 = y * y, z2 = z * z;

        const float s3  = 1.7320508075688772f;
        const float s15 = 3.872983346207417f;
        float* S = s_sh + tid * 17;
        S[0]  = 1.f;
        S[1]  = s3 * x;
        S[2]  = s3 * y;
        S[3]  = s3 * z;
        S[4]  = s15 * x * y;
        S[5]  = s15 * y * z;
        S[6]  = 1.118033988749895f * (3.f * z2 - 1.f);
        S[7]  = s15 * x * z;
        S[8]  = 1.9364916731037085f * (x2 - y2);
        S[9]  = 2.091650066335189f * y * (3.f * x2 - y2);
        S[10] = 10.246950765959598f * x * y * z;
        S[11] = 1.6201851746019651f * y * (5.f * z2 - 1.f);
        S[12] = 1.3228756555322954f * (5.f * z2 * z - 3.f * z);
        S[13] = 1.6201851746019651f * x * (5.f * z2 - 1.f);
        S[14] = 5.123475382979799f * z * (x2 - y2);
        S[15] = 2.091650066335189f * x * (x2 - 3.f * y2);

        float f = r * ((float)(TN - 1) / RMAXF);
        f = fminf(f, (float)(TN - 1));
        int i0 = (int)f;
        i0 = min(i0, TN - 2);
        s_i0[tid] = i0;
        s_w[tid] = f - (float)i0;
        s_src[tid] = src_g;
        s_dst[tid] = dst_g;
    } else {
        float* S = s_sh + tid * 17;
#pragma unroll
        for (int m = 0; m < 16; m++) S[m] = 0.f;
        s_i0[tid] = 0;
        s_w[tid] = 0.f;
        s_src[tid] = 0;
        s_dst[tid] = -1;
    }
    __syncthreads();

    // ---- Phase 1.5: half-warp = edge; coalesced table read + reduce ----
    {
        int lane = tid & 31;
        int m = lane & 15;
        int hw = (tid >> 5) * 2 + (lane >> 4);  // half-warp id 0..15
#pragma unroll 2
        for (int k = 0; k < 16; k++) {
            int el = hw * 16 + k;
            int i0 = s_i0[el];
            float w = s_w[el];
            float shm = s_sh[el * 17 + m];
            const float* G = g_table + i0 * 48 + m;
#pragma unroll
            for (int t = 0; t < 3; t++) {
                float g0 = __ldg(G + t * 16);
                float g1 = __ldg(G + 48 + t * 16);
                float v = shm * fmaf(w, g1 - g0, g0);
                v += __shfl_xor_sync(0xFFFFFFFFu, v, 1);
                v += __shfl_xor_sync(0xFFFFFFFFu, v, 2);
                v += __shfl_xor_sync(0xFFFFFFFFu, v, 4);
                v += __shfl_xor_sync(0xFFFFFFFFu, v, 8);
                if (m == 0) s_sc[el * 4 + t] = v;
            }
        }
    }
    __syncthreads();

    // ---- Phase 2: warp = edge; fp16 gather + fp32 vector red scatter ----
    int lane = tid & 31;
    int base = (tid >> 5) * 32;
    size_t repT2 = (size_t)AB * 64;   // half2 elements per t-plane
    const __half2* rep2 = (const __half2*)rep16;
#pragma unroll 4
    for (int k = 0; k < 32; k++) {
        int el = base + k;
        int dst = s_dst[el];
        if (dst < 0) continue;  // warp-uniform (only in last block)
        float c0 = s_sc[el * 4 + 0];
        float c1 = s_sc[el * 4 + 1];
        float c2 = s_sc[el * 4 + 2];
        int src = s_src[el];
        // each lane: 2 half2 (= 4 values) per t-plane, 8-byte loads
        const __half2* p0 = rep2 + (size_t)src * 64 + lane * 2;
        uint2 u0 = __ldg((const uint2*)p0);
        uint2 u1 = __ldg((const uint2*)(p0 + repT2));
        uint2 u2 = __ldg((const uint2*)(p0 + 2 * repT2));
        float2 a0 = __half22float2(*(__half2*)&u0.x);
        float2 b0 = __half22float2(*(__half2*)&u0.y);
        float2 a1 = __half22float2(*(__half2*)&u1.x);
        float2 b1 = __half22float2(*(__half2*)&u1.y);
        float2 a2 = __half22float2(*(__half2*)&u2.x);
        float2 b2 = __half22float2(*(__half2*)&u2.y);
        float4 m;
        m.x = fmaf(c0, a0.x, fmaf(c1, a1.x, c2 * a2.x));
        m.y = fmaf(c0, a0.y, fmaf(c1, a1.y, c2 * a2.y));
        m.z = fmaf(c0, b0.x, fmaf(c1, b1.x, c2 * b2.x));
        m.w = fmaf(c0, b0.y, fmaf(c1, b1.y, c2 * b2.y));
        float* dptr = probes + (size_t)dst * 128 + lane * 4;
        asm volatile("red.global.add.v4.f32 [%0], {%1, %2, %3, %4};"
                     :: "l"(dptr), "f"(m.x), "f"(m.y), "f"(m.z), "f"(m.w)
                     : "memory");
        if (lane == 0) {
            float ov = fmaf(c0, rw_table[src],
                       fmaf(c1, rw_table[AB + src],
                            c2 * rw_table[2 * AB + src]));
            atomicAdd(out + dst, ov);
        }
    }
}

extern "C" void kernel_launch(void* const* d_in, const int* in_sizes, int n_in,
                              void* d_out, int out_size)
{
    const float* atom_xyz  = (const float*)d_in[0];
    const float* probe_xyz = (const float*)d_in[1];
    const int*   edges     = (const int*)d_in[2];
    const float* ped       = (const float*)d_in[3];
    const float* cell      = (const float*)d_in[4];
    const float* atom_rep  = (const float*)d_in[8];
    const float* w1        = (const float*)d_in[9];
    const float* w2        = (const float*)d_in[10];
    const float* w_out     = (const float*)d_in[11];

    int B         = in_sizes[4] / 9;
    int n_atoms   = in_sizes[0] / (3 * B);
    int n_probes  = in_sizes[1] / (3 * B);
    int n_edges_b = in_sizes[2] / (2 * B);
    int E  = B * n_edges_b;
    int AB = B * n_atoms;
    int P  = B * n_probes;

    float* out    = (float*)d_out;      // first P: (B,P) potential
    float* probes = out + P;            // next P*128: probe features

    cudaMemsetAsync(d_out, 0, (size_t)(P + (size_t)P * 128) * sizeof(float), 0);

    // table build (flat parallel) + rep16 + rw precompute
    rb_kernel<<<(TN * 10 + 255) / 256, 256>>>();
    act_kernel<<<(TN * 300 + 255) / 256, 256>>>(w1);
    gtab_kernel<<<(TN * 48 + 255) / 256, 256>>>(w2);
    rep16_kernel<<<(3 * AB * 64 + 255) / 256, 256>>>(atom_rep, 3 * AB * 64);
    rw_kernel<<<(3 * AB * 32 + 255) / 256, 256>>>(atom_rep, w_out, 3 * AB);

    edge_kernel<<<(E + 255) / 256, 256>>>(atom_xyz, probe_xyz, edges, ped, cell,
                                          probes, out,
                                          E, n_edges_b, n_atoms, n_probes, AB);
}

// round 8
// speedup vs baseline: 1.4126x; 1.0355x over previous
#include <cuda_runtime.h>
#include <cuda_fp16.h>

#define TN 2048
#define RMAXF 8.0f
#define MAXAB 32768

// Radial table: g[i][t*16+m] = (silu(rb(r_i)@w1[t]) @ w2[t])[m] / sqrt(20)
// g(r)==0 exactly for r >~ 6.5 (gaussians vanish, silu(0)=0) so clamping
// r>RMAXF into the zero tail is exact.
__device__ float g_table[TN * 48];
// lerp-pair fp16 table: g16[i*48+o] = (g[i][o], g[i+1][o])
__device__ __half2 g16[TN * 48];
__device__ float rb_tab[TN * 10];
__device__ float act_tab[TN * 300];
// rw[t*AB + a] = dot(atom_rep[t][a][:], w_out)
__device__ float rw_table[3 * MAXAB];
// fp16 copy of atom_rep (halves gather traffic; accumulation stays fp32)
__device__ __half rep16[3 * MAXAB * 128];

// ---------------- table build: flat, embarrassingly parallel ----------------
__global__ void rb_kernel()
{
    int id = blockIdx.x * blockDim.x + threadIdx.x;
    if (id >= TN * 10) return;
    int i = id / 10, k = id % 10;
    float r = (float)i * (RMAXF / (float)(TN - 1));
    const float step = 4.0f / 9.0f;
    float d = (r - (float)k * step) / step;
    rb_tab[id] = expf(-d * d) * 1.12f;
}

__global__ void act_kernel(const float* __restrict__ w1)
{
    int id = blockIdx.x * blockDim.x + threadIdx.x;
    if (id >= TN * 300) return;
    int i = id / 300, rem = id % 300;
    int t = rem / 100, j = rem % 100;
    const float* RB = rb_tab + i * 10;
    const float* W1 = w1 + t * 1000 + j;  // stride 100 over k
    float a = 0.f;
#pragma unroll
    for (int k = 0; k < 10; k++)
        a = fmaf(__ldg(RB + k), __ldg(W1 + k * 100), a);
    act_tab[id] = a / (1.f + expf(-a));
}

__global__ void gtab_kernel(const float* __restrict__ w2)
{
    int id = blockIdx.x * blockDim.x + threadIdx.x;
    if (id >= TN * 48) return;
    int i = id / 48, o = id % 48;
    int t = o >> 4, m = o & 15;
    const float* A = act_tab + i * 300 + t * 100;
    const float* W = w2 + t * 1600 + m;   // stride 16 over j
    float h0 = 0.f, h1 = 0.f;
#pragma unroll 4
    for (int j = 0; j < 100; j += 2) {
        h0 = fmaf(__ldg(A + j),     __ldg(W + j * 16),       h0);
        h1 = fmaf(__ldg(A + j + 1), __ldg(W + (j + 1) * 16), h1);
    }
    g_table[id] = (h0 + h1) * 0.22360679774997896f;  // 1/sqrt(20)
}

__global__ void pack_kernel()
{
    int id = blockIdx.x * blockDim.x + threadIdx.x;
    if (id >= TN * 48) return;
    int i = id / 48, o = id % 48;
    float g0 = g_table[id];
    float g1 = g_table[min(i + 1, TN - 1) * 48 + o];
    g16[id] = __floats2half2_rn(g0, g1);
}

// ---------------- fused prep: rep16 convert + rw dot (one pass) -------------
__global__ void prep_rep_kernel(const float* __restrict__ atom_rep,
                                const float* __restrict__ w_out, int rows)
{
    int g = blockIdx.x * blockDim.x + threadIdx.x;
    int row = g >> 5;
    int lane = g & 31;
    if (row >= rows) return;
    float4 a = __ldg((const float4*)atom_rep + (size_t)row * 32 + lane);
    // fp16 copy
    __half2 h0 = __floats2half2_rn(a.x, a.y);
    __half2 h1 = __floats2half2_rn(a.z, a.w);
    uint2 u;
    u.x = *(unsigned*)&h0;
    u.y = *(unsigned*)&h1;
    ((uint2*)rep16)[(size_t)row * 32 + lane] = u;
    // rw dot
    float4 wv = __ldg((const float4*)w_out + lane);
    float s = fmaf(a.x, wv.x, fmaf(a.y, wv.y, fmaf(a.z, wv.z, a.w * wv.w)));
#pragma unroll
    for (int off = 16; off > 0; off >>= 1)
        s += __shfl_xor_sync(0xFFFFFFFFu, s, off);
    if (lane == 0) rw_table[row] = s;
}

// ---------------- fused edge kernel ------------------------------------------
__global__ void __launch_bounds__(256) edge_kernel(
    const float* __restrict__ atom_xyz,
    const float* __restrict__ probe_xyz,
    const int*   __restrict__ edges,
    const float* __restrict__ ped,
    const float* __restrict__ cell,
    float* __restrict__ probes,
    float* __restrict__ out,
    int E, int n_edges_b, int n_atoms, int n_probes, int AB)
{
    __shared__ float s_sh[256 * 17];   // sh[16] per edge, pitch 17 (bank-safe)
    __shared__ int   s_i0[256];
    __shared__ float s_w[256];
    __shared__ int   s_src[256];
    __shared__ int   s_dst[256];
    __shared__ float s_sc[256 * 4];    // 3 scalars per edge, pitch 4

    int tid = threadIdx.x;
    int e = blockIdx.x * 256 + tid;

    // ---- Phase 1: thread = edge; geometry + SH + table index ----
    if (e < E) {
        int b = e / n_edges_b;
        int2 se = ((const int2*)edges)[e];
        int src_g = b * n_atoms + se.x;
        int dst_g = b * n_probes + se.y;
        float px = ped[3 * e], py = ped[3 * e + 1], pz = ped[3 * e + 2];
        const float* C = cell + b * 9;
        float dx = fmaf(px, __ldg(C + 0), fmaf(py, __ldg(C + 3), pz * __ldg(C + 6)));
        float dy = fmaf(px, __ldg(C + 1), fmaf(py, __ldg(C + 4), pz * __ldg(C + 7)));
        float dz = fmaf(px, __ldg(C + 2), fmaf(py, __ldg(C + 5), pz * __ldg(C + 8)));
        float vx = probe_xyz[3 * dst_g + 0] - atom_xyz[3 * src_g + 0] - dx;
        float vy = probe_xyz[3 * dst_g + 1] - atom_xyz[3 * src_g + 1] - dy;
        float vz = probe_xyz[3 * dst_g + 2] - atom_xyz[3 * src_g + 2] - dz;
        float r2 = fmaf(vx, vx, fmaf(vy, vy, vz * vz));
        float r = sqrtf(r2);
        float rinv = 1.0f / fmaxf(r, 1e-9f);
        float x = vx * rinv, y = vy * rinv, z = vz * rinv;
        float x2 = x * x, y2 = y * y, z2 = z * z;

        const float s3  = 1.7320508075688772f;
        const float s15 = 3.872983346207417f;
        float* S = s_sh + tid * 17;
        S[0]  = 1.f;
        S[1]  = s3 * x;
        S[2]  = s3 * y;
        S[3]  = s3 * z;
        S[4]  = s15 * x * y;
        S[5]  = s15 * y * z;
        S[6]  = 1.118033988749895f * (3.f * z2 - 1.f);
        S[7]  = s15 * x * z;
        S[8]  = 1.9364916731037085f * (x2 - y2);
        S[9]  = 2.091650066335189f * y * (3.f * x2 - y2);
        S[10] = 10.246950765959598f * x * y * z;
        S[11] = 1.6201851746019651f * y * (5.f * z2 - 1.f);
        S[12] = 1.3228756555322954f * (5.f * z2 * z - 3.f * z);
        S[13] = 1.6201851746019651f * x * (5.f * z2 - 1.f);
        S[14] = 5.123475382979799f * z * (x2 - y2);
        S[15] = 2.091650066335189f * x * (x2 - 3.f * y2);

        float f = r * ((float)(TN - 1) / RMAXF);
        f = fminf(f, (float)(TN - 1));
        int i0 = (int)f;
        i0 = min(i0, TN - 2);
        s_i0[tid] = i0;
        s_w[tid] = f - (float)i0;
        s_src[tid] = src_g;
        s_dst[tid] = dst_g;
    } else {
        float* S = s_sh + tid * 17;
#pragma unroll
        for (int m = 0; m < 16; m++) S[m] = 0.f;
        s_i0[tid] = 0;
        s_w[tid] = 0.f;
        s_src[tid] = 0;
        s_dst[tid] = -1;
    }
    __syncthreads();

    // ---- Phase 1.5: half-warp = edge; one lerp-pair load per t ----
    {
        int lane = tid & 31;
        int m = lane & 15;
        int hw = (tid >> 5) * 2 + (lane >> 4);  // half-warp id 0..15
#pragma unroll 2
        for (int k = 0; k < 16; k++) {
            int el = hw * 16 + k;
            int i0 = s_i0[el];
            float w = s_w[el];
            float shm = s_sh[el * 17 + m];
            const __half2* G = g16 + i0 * 48 + m;
#pragma unroll
            for (int t = 0; t < 3; t++) {
                float2 gpair = __half22float2(__ldg(G + t * 16));
                float v = shm * fmaf(w, gpair.y - gpair.x, gpair.x);
                v += __shfl_xor_sync(0xFFFFFFFFu, v, 1);
                v += __shfl_xor_sync(0xFFFFFFFFu, v, 2);
                v += __shfl_xor_sync(0xFFFFFFFFu, v, 4);
                v += __shfl_xor_sync(0xFFFFFFFFu, v, 8);
                if (m == 0) s_sc[el * 4 + t] = v;
            }
        }
    }
    __syncthreads();

    // ---- Phase 2: warp = edge; fp16 gather + fp32 vector red scatter ----
    int lane = tid & 31;
    int base = (tid >> 5) * 32;
    size_t repT2 = (size_t)AB * 64;   // half2 elements per t-plane
    const __half2* rep2 = (const __half2*)rep16;
#pragma unroll 4
    for (int k = 0; k < 32; k++) {
        int el = base + k;
        int dst = s_dst[el];
        if (dst < 0) continue;  // warp-uniform (only in last block)
        float c0 = s_sc[el * 4 + 0];
        float c1 = s_sc[el * 4 + 1];
        float c2 = s_sc[el * 4 + 2];
        int src = s_src[el];
        // each lane: 2 half2 (= 4 values) per t-plane, 8-byte loads
        const __half2* p0 = rep2 + (size_t)src * 64 + lane * 2;
        uint2 u0 = __ldg((const uint2*)p0);
        uint2 u1 = __ldg((const uint2*)(p0 + repT2));
        uint2 u2 = __ldg((const uint2*)(p0 + 2 * repT2));
        float2 a0 = __half22float2(*(__half2*)&u0.x);
        float2 b0 = __half22float2(*(__half2*)&u0.y);
        float2 a1 = __half22float2(*(__half2*)&u1.x);
        float2 b1 = __half22float2(*(__half2*)&u1.y);
        float2 a2 = __half22float2(*(__half2*)&u2.x);
        float2 b2 = __half22float2(*(__half2*)&u2.y);
        float4 m;
        m.x = fmaf(c0, a0.x, fmaf(c1, a1.x, c2 * a2.x));
        m.y = fmaf(c0, a0.y, fmaf(c1, a1.y, c2 * a2.y));
        m.z = fmaf(c0, b0.x, fmaf(c1, b1.x, c2 * b2.x));
        m.w = fmaf(c0, b0.y, fmaf(c1, b1.y, c2 * b2.y));
        float* dptr = probes + (size_t)dst * 128 + lane * 4;
        asm volatile("red.global.add.v4.f32 [%0], {%1, %2, %3, %4};"
                     :: "l"(dptr), "f"(m.x), "f"(m.y), "f"(m.z), "f"(m.w)
                     : "memory");
        if (lane == 0) {
            float ov = fmaf(c0, rw_table[src],
                       fmaf(c1, rw_table[AB + src],
                            c2 * rw_table[2 * AB + src]));
            atomicAdd(out + dst, ov);
        }
    }
}

extern "C" void kernel_launch(void* const* d_in, const int* in_sizes, int n_in,
                              void* d_out, int out_size)
{
    const float* atom_xyz  = (const float*)d_in[0];
    const float* probe_xyz = (const float*)d_in[1];
    const int*   edges     = (const int*)d_in[2];
    const float* ped       = (const float*)d_in[3];
    const float* cell      = (const float*)d_in[4];
    const float* atom_rep  = (const float*)d_in[8];
    const float* w1        = (const float*)d_in[9];
    const float* w2        = (const float*)d_in[10];
    const float* w_out     = (const float*)d_in[11];

    int B         = in_sizes[4] / 9;
    int n_atoms   = in_sizes[0] / (3 * B);
    int n_probes  = in_sizes[1] / (3 * B);
    int n_edges_b = in_sizes[2] / (2 * B);
    int E  = B * n_edges_b;
    int AB = B * n_atoms;
    int P  = B * n_probes;

    float* out    = (float*)d_out;      // first P: (B,P) potential
    float* probes = out + P;            // next P*128: probe features

    cudaMemsetAsync(d_out, 0, (size_t)(P + (size_t)P * 128) * sizeof(float), 0);

    // table build (flat parallel) + fused rep16/rw prep
    rb_kernel<<<(TN * 10 + 255) / 256, 256>>>();
    act_kernel<<<(TN * 300 + 255) / 256, 256>>>(w1);
    gtab_kernel<<<(TN * 48 + 255) / 256, 256>>>(w2);
    pack_kernel<<<(TN * 48 + 255) / 256, 256>>>();
    prep_rep_kernel<<<(3 * AB * 32 + 255) / 256, 256>>>(atom_rep, w_out, 3 * AB);

    edge_kernel<<<(E + 255) / 256, 256>>>(atom_xyz, probe_xyz, edges, ped, cell,
                                          probes, out,
                                          E, n_edges_b, n_atoms, n_probes, AB);
}

// round 9
// speedup vs baseline: 1.4748x; 1.0440x over previous
#include <cuda_runtime.h>
#include <cuda_fp16.h>

#define TN 2048
#define RMAXF 8.0f
#define MAXAB 32768
#define MAXE  640000
#define MAXP  262144

// Radial table: g[i][t*16+m] = (silu(rb(r_i)@w1[t]) @ w2[t])[m] / sqrt(20)
// g(r)==0 exactly for r >~ 6.5, so clamping r>RMAXF into the zero tail is exact.
__device__ float g_table[TN * 48];
__device__ __half2 g16[TN * 48];        // (g[i][o], g[i+1][o]) lerp pairs
__device__ float rb_tab[TN * 10];
__device__ float act_tab[TN * 300];
__device__ float rw_table[3 * MAXAB];   // dot(atom_rep[t][a], w_out)
__device__ __half rep16[3 * MAXAB * 128];
// per-probe linked list of edges
__device__ float4 rec[MAXE];            // (c0,c1,c2, src-as-float)
__device__ int    nxt[MAXE];
__device__ int    head[MAXP];

// ---------------- table build ------------------------------------------------
__global__ void rb_kernel()
{
    int id = blockIdx.x * blockDim.x + threadIdx.x;
    if (id >= TN * 10) return;
    int i = id / 10, k = id % 10;
    float r = (float)i * (RMAXF / (float)(TN - 1));
    const float step = 4.0f / 9.0f;
    float d = (r - (float)k * step) / step;
    rb_tab[id] = expf(-d * d) * 1.12f;
}

__global__ void act_kernel(const float* __restrict__ w1)
{
    int id = blockIdx.x * blockDim.x + threadIdx.x;
    if (id >= TN * 300) return;
    int i = id / 300, rem = id % 300;
    int t = rem / 100, j = rem % 100;
    const float* RB = rb_tab + i * 10;
    const float* W1 = w1 + t * 1000 + j;
    float a = 0.f;
#pragma unroll
    for (int k = 0; k < 10; k++)
        a = fmaf(__ldg(RB + k), __ldg(W1 + k * 100), a);
    act_tab[id] = a / (1.f + expf(-a));
}

__global__ void gtab_kernel(const float* __restrict__ w2)
{
    int id = blockIdx.x * blockDim.x + threadIdx.x;
    if (id >= TN * 48) return;
    int i = id / 48, o = id % 48;
    int t = o >> 4, m = o & 15;
    const float* A = act_tab + i * 300 + t * 100;
    const float* W = w2 + t * 1600 + m;
    float h0 = 0.f, h1 = 0.f;
#pragma unroll 4
    for (int j = 0; j < 100; j += 2) {
        h0 = fmaf(__ldg(A + j),     __ldg(W + j * 16),       h0);
        h1 = fmaf(__ldg(A + j + 1), __ldg(W + (j + 1) * 16), h1);
    }
    g_table[id] = (h0 + h1) * 0.22360679774997896f;  // 1/sqrt(20)
}

__global__ void pack_kernel()
{
    int id = blockIdx.x * blockDim.x + threadIdx.x;
    if (id >= TN * 48) return;
    int i = id / 48, o = id % 48;
    float g0 = g_table[id];
    float g1 = g_table[min(i + 1, TN - 1) * 48 + o];
    g16[id] = __floats2half2_rn(g0, g1);
}

// ---------------- prep: rep16 convert + rw dot + head init ------------------
__global__ void prep_rep_kernel(const float* __restrict__ atom_rep,
                                const float* __restrict__ w_out, int rows)
{
    int g = blockIdx.x * blockDim.x + threadIdx.x;
    int row = g >> 5;
    int lane = g & 31;
    if (row >= rows) return;
    float4 a = __ldg((const float4*)atom_rep + (size_t)row * 32 + lane);
    __half2 h0 = __floats2half2_rn(a.x, a.y);
    __half2 h1 = __floats2half2_rn(a.z, a.w);
    uint2 u;
    u.x = *(unsigned*)&h0;
    u.y = *(unsigned*)&h1;
    ((uint2*)rep16)[(size_t)row * 32 + lane] = u;
    float4 wv = __ldg((const float4*)w_out + lane);
    float s = fmaf(a.x, wv.x, fmaf(a.y, wv.y, fmaf(a.z, wv.z, a.w * wv.w)));
#pragma unroll
    for (int off = 16; off > 0; off >>= 1)
        s += __shfl_xor_sync(0xFFFFFFFFu, s, off);
    if (lane == 0) rw_table[row] = s;
}

__global__ void init_head_kernel(int P)
{
    int i = blockIdx.x * blockDim.x + threadIdx.x;
    if (i < P) head[i] = -1;
}

// ---------------- phase A: per-edge scalars + linked-list insert -------------
__global__ void __launch_bounds__(256) phaseA_kernel(
    const float* __restrict__ atom_xyz,
    const float* __restrict__ probe_xyz,
    const int*   __restrict__ edges,
    const float* __restrict__ ped,
    const float* __restrict__ cell,
    int E, int n_edges_b, int n_atoms, int n_probes)
{
    __shared__ float s_sh[256 * 17];
    __shared__ int   s_i0[256];
    __shared__ float s_w[256];
    __shared__ int   s_src[256];
    __shared__ int   s_dst[256];
    __shared__ float s_sc[256 * 4];

    int tid = threadIdx.x;
    int e = blockIdx.x * 256 + tid;

    if (e < E) {
        int b = e / n_edges_b;
        int2 se = ((const int2*)edges)[e];
        int src_g = b * n_atoms + se.x;
        int dst_g = b * n_probes + se.y;
        float px = ped[3 * e], py = ped[3 * e + 1], pz = ped[3 * e + 2];
        const float* C = cell + b * 9;
        float dx = fmaf(px, __ldg(C + 0), fmaf(py, __ldg(C + 3), pz * __ldg(C + 6)));
        float dy = fmaf(px, __ldg(C + 1), fmaf(py, __ldg(C + 4), pz * __ldg(C + 7)));
        float dz = fmaf(px, __ldg(C + 2), fmaf(py, __ldg(C + 5), pz * __ldg(C + 8)));
        float vx = probe_xyz[3 * dst_g + 0] - atom_xyz[3 * src_g + 0] - dx;
        float vy = probe_xyz[3 * dst_g + 1] - atom_xyz[3 * src_g + 1] - dy;
        float vz = probe_xyz[3 * dst_g + 2] - atom_xyz[3 * src_g + 2] - dz;
        float r2 = fmaf(vx, vx, fmaf(vy, vy, vz * vz));
        float r = sqrtf(r2);
        float rinv = 1.0f / fmaxf(r, 1e-9f);
        float x = vx * rinv, y = vy * rinv, z = vz * rinv;
        float x2 = x * x, y2 = y * y, z2 = z * z;

        const float s3  = 1.7320508075688772f;
        const float s15 = 3.872983346207417f;
        float* S = s_sh + tid * 17;
        S[0]  = 1.f;
        S[1]  = s3 * x;
        S[2]  = s3 * y;
        S[3]  = s3 * z;
        S[4]  = s15 * x * y;
        S[5]  = s15 * y * z;
        S[6]  = 1.118033988749895f * (3.f * z2 - 1.f);
        S[7]  = s15 * x * z;
        S[8]  = 1.9364916731037085f * (x2 - y2);
        S[9]  = 2.091650066335189f * y * (3.f * x2 - y2);
        S[10] = 10.246950765959598f * x * y * z;
        S[11] = 1.6201851746019651f * y * (5.f * z2 - 1.f);
        S[12] = 1.3228756555322954f * (5.f * z2 * z - 3.f * z);
        S[13] = 1.6201851746019651f * x * (5.f * z2 - 1.f);
        S[14] = 5.123475382979799f * z * (x2 - y2);
        S[15] = 2.091650066335189f * x * (x2 - 3.f * y2);

        float f = r * ((float)(TN - 1) / RMAXF);
        f = fminf(f, (float)(TN - 1));
        int i0 = (int)f;
        i0 = min(i0, TN - 2);
        s_i0[tid] = i0;
        s_w[tid] = f - (float)i0;
        s_src[tid] = src_g;
        s_dst[tid] = dst_g;
    } else {
        float* S = s_sh + tid * 17;
#pragma unroll
        for (int m = 0; m < 16; m++) S[m] = 0.f;
        s_i0[tid] = 0;
        s_w[tid] = 0.f;
        s_src[tid] = 0;
        s_dst[tid] = -1;
    }
    __syncthreads();

    // half-warp per edge: one lerp-pair load per t + 16-lane reduce
    {
        int lane = tid & 31;
        int m = lane & 15;
        int hw = (tid >> 5) * 2 + (lane >> 4);
#pragma unroll 2
        for (int k = 0; k < 16; k++) {
            int el = hw * 16 + k;
            int i0 = s_i0[el];
            float w = s_w[el];
            float shm = s_sh[el * 17 + m];
            const __half2* G = g16 + i0 * 48 + m;
#pragma unroll
            for (int t = 0; t < 3; t++) {
                float2 gpair = __half22float2(__ldg(G + t * 16));
                float v = shm * fmaf(w, gpair.y - gpair.x, gpair.x);
                v += __shfl_xor_sync(0xFFFFFFFFu, v, 1);
                v += __shfl_xor_sync(0xFFFFFFFFu, v, 2);
                v += __shfl_xor_sync(0xFFFFFFFFu, v, 4);
                v += __shfl_xor_sync(0xFFFFFFFFu, v, 8);
                if (m == 0) s_sc[el * 4 + t] = v;
            }
        }
    }
    __syncthreads();

    // linked-list insert: rec slot = e (coalesced), push onto head[dst]
    if (e < E) {
        rec[e] = make_float4(s_sc[tid * 4 + 0], s_sc[tid * 4 + 1],
                             s_sc[tid * 4 + 2], __int_as_float(s_src[tid]));
        nxt[e] = atomicExch(&head[s_dst[tid]], e);
    }
}

// ---------------- phase B: warp per probe, accumulate in regs, write once ----
__global__ void __launch_bounds__(256) phaseB_kernel(
    float* __restrict__ probes, float* __restrict__ out, int P, int AB)
{
    int g = blockIdx.x * blockDim.x + threadIdx.x;
    int p = g >> 5;
    int lane = g & 31;
    if (p >= P) return;

    float4 acc = make_float4(0.f, 0.f, 0.f, 0.f);
    float ov = 0.f;
    size_t repT2 = (size_t)AB * 64;
    const __half2* rep2 = (const __half2*)rep16;

    int e = head[p];
    while (e >= 0) {
        float4 c = __ldg(&rec[e]);           // broadcast (same addr all lanes)
        int src = __float_as_int(c.w);
        const __half2* p0 = rep2 + (size_t)src * 64 + lane * 2;
        uint2 u0 = __ldg((const uint2*)p0);
        uint2 u1 = __ldg((const uint2*)(p0 + repT2));
        uint2 u2 = __ldg((const uint2*)(p0 + 2 * repT2));
        float2 a0 = __half22float2(*(__half2*)&u0.x);
        float2 b0 = __half22float2(*(__half2*)&u0.y);
        float2 a1 = __half22float2(*(__half2*)&u1.x);
        float2 b1 = __half22float2(*(__half2*)&u1.y);
        float2 a2 = __half22float2(*(__half2*)&u2.x);
        float2 b2 = __half22float2(*(__half2*)&u2.y);
        acc.x += fmaf(c.x, a0.x, fmaf(c.y, a1.x, c.z * a2.x));
        acc.y += fmaf(c.x, a0.y, fmaf(c.y, a1.y, c.z * a2.y));
        acc.z += fmaf(c.x, b0.x, fmaf(c.y, b1.x, c.z * b2.x));
        acc.w += fmaf(c.x, b0.y, fmaf(c.y, b1.y, c.z * b2.y));
        if (lane == 0)
            ov += fmaf(c.x, rw_table[src],
                  fmaf(c.y, rw_table[AB + src], c.z * rw_table[2 * AB + src]));
        e = __ldg(&nxt[e]);
    }
    ((float4*)(probes + (size_t)p * 128))[lane] = acc;
    if (lane == 0) out[p] = ov;
}

extern "C" void kernel_launch(void* const* d_in, const int* in_sizes, int n_in,
                              void* d_out, int out_size)
{
    const float* atom_xyz  = (const float*)d_in[0];
    const float* probe_xyz = (const float*)d_in[1];
    const int*   edges     = (const int*)d_in[2];
    const float* ped       = (const float*)d_in[3];
    const float* cell      = (const float*)d_in[4];
    const float* atom_rep  = (const float*)d_in[8];
    const float* w1        = (const float*)d_in[9];
    const float* w2        = (const float*)d_in[10];
    const float* w_out     = (const float*)d_in[11];

    int B         = in_sizes[4] / 9;
    int n_atoms   = in_sizes[0] / (3 * B);
    int n_probes  = in_sizes[1] / (3 * B);
    int n_edges_b = in_sizes[2] / (2 * B);
    int E  = B * n_edges_b;
    int AB = B * n_atoms;
    int P  = B * n_probes;

    float* out    = (float*)d_out;      // first P: (B,P) potential
    float* probes = out + P;            // next P*128: probe features

    // table build + prep (no memset needed: phase B writes every element)
    rb_kernel<<<(TN * 10 + 255) / 256, 256>>>();
    act_kernel<<<(TN * 300 + 255) / 256, 256>>>(w1);
    gtab_kernel<<<(TN * 48 + 255) / 256, 256>>>(w2);
    pack_kernel<<<(TN * 48 + 255) / 256, 256>>>();
    prep_rep_kernel<<<(3 * AB * 32 + 255) / 256, 256>>>(atom_rep, w_out, 3 * AB);
    init_head_kernel<<<(P + 255) / 256, 256>>>(P);

    phaseA_kernel<<<(E + 255) / 256, 256>>>(atom_xyz, probe_xyz, edges, ped,
                                            cell, E, n_edges_b, n_atoms,
                                            n_probes);
    phaseB_kernel<<<(P * 32 + 255) / 256, 256>>>(probes, out, P, AB);
}

// round 10
// speedup vs baseline: 1.9338x; 1.3113x over previous
#include <cuda_runtime.h>
#include <cuda_fp16.h>

#define TN 2048
#define RMAXF 8.0f
#define ICUT 1535            /* table index at r=6.0; g beyond is ~1e-8 */
#define MAXAB 32768
#define MAXE  640000
#define MAXP  262144

// Radial table (fp16 lerp pairs): g16[i*48+o] = (g[i][o], g[i+1][o]),
// g[i][t*16+m] = (silu(rb(r_i)@w1[t]) @ w2[t])[m] / sqrt(20).
// g(r)==~0 for r > 5.8, so dropping r>6 edges and clamping r>RMAXF is safe.
__device__ __half2 g16[TN * 48];
__device__ float rb_tab[TN * 10];
__device__ float act_tab[TN * 300];
__device__ float rw_table[3 * MAXAB];   // dot(atom_rep[t][a], w_out)
__device__ __half rep16[3 * MAXAB * 128];
// per-probe linked list of contributing edges
__device__ float4 rec[MAXE];            // (c0,c1,c2, src-as-float)
__device__ int    nxt[MAXE];
__device__ int    head[MAXP];

// ---------------- 1: radial basis table -------------------------------------
__global__ void rb_kernel()
{
    int id = blockIdx.x * blockDim.x + threadIdx.x;
    if (id >= TN * 10) return;
    int i = id / 10, k = id % 10;
    float r = (float)i * (RMAXF / (float)(TN - 1));
    const float step = 4.0f / 9.0f;
    float d = (r - (float)k * step) / step;
    rb_tab[id] = expf(-d * d) * 1.12f;
}

// ---------------- 2: hidden activations + head init -------------------------
__global__ void act_kernel(const float* __restrict__ w1, int P)
{
    int id = blockIdx.x * blockDim.x + threadIdx.x;
    if (id < P) head[id] = -1;
    if (id >= TN * 300) return;
    int i = id / 300, rem = id % 300;
    int t = rem / 100, j = rem % 100;
    const float* RB = rb_tab + i * 10;
    const float* W1 = w1 + t * 1000 + j;
    float a = 0.f;
#pragma unroll
    for (int k = 0; k < 10; k++)
        a = fmaf(__ldg(RB + k), __ldg(W1 + k * 100), a);
    act_tab[id] = a / (1.f + expf(-a));
}

// ---------------- 3: output table, fp16 lerp pairs directly -----------------
__global__ void gtab16_kernel(const float* __restrict__ w2)
{
    int id = blockIdx.x * blockDim.x + threadIdx.x;
    if (id >= TN * 48) return;
    int i = id / 48, o = id % 48;
    int t = o >> 4, m = o & 15;
    const float* A0 = act_tab + i * 300 + t * 100;
    const float* A1 = act_tab + min(i + 1, TN - 1) * 300 + t * 100;
    const float* W = w2 + t * 1600 + m;
    float h0 = 0.f, h1 = 0.f;
#pragma unroll 4
    for (int j = 0; j < 100; j++) {
        float wv = __ldg(W + j * 16);
        h0 = fmaf(__ldg(A0 + j), wv, h0);
        h1 = fmaf(__ldg(A1 + j), wv, h1);
    }
    const float scale = 0.22360679774997896f;  // 1/sqrt(20)
    g16[id] = __floats2half2_rn(h0 * scale, h1 * scale);
}

// ---------------- 4: phase A — per-edge scalars + list insert ---------------
__global__ void __launch_bounds__(256) phaseA_kernel(
    const float* __restrict__ atom_xyz,
    const float* __restrict__ probe_xyz,
    const int*   __restrict__ edges,
    const float* __restrict__ ped,
    const float* __restrict__ cell,
    int E, int n_edges_b, int n_atoms, int n_probes)
{
    __shared__ float s_sh[256 * 17];
    __shared__ int   s_i0[256];
    __shared__ float s_w[256];
    __shared__ int   s_src[256];
    __shared__ int   s_dst[256];
    __shared__ float s_sc[256 * 4];

    int tid = threadIdx.x;
    int e = blockIdx.x * 256 + tid;

    if (e < E) {
        int b = e / n_edges_b;
        int2 se = ((const int2*)edges)[e];
        int src_g = b * n_atoms + se.x;
        int dst_g = b * n_probes + se.y;
        float px = ped[3 * e], py = ped[3 * e + 1], pz = ped[3 * e + 2];
        const float* C = cell + b * 9;
        float dx = fmaf(px, __ldg(C + 0), fmaf(py, __ldg(C + 3), pz * __ldg(C + 6)));
        float dy = fmaf(px, __ldg(C + 1), fmaf(py, __ldg(C + 4), pz * __ldg(C + 7)));
        float dz = fmaf(px, __ldg(C + 2), fmaf(py, __ldg(C + 5), pz * __ldg(C + 8)));
        float vx = probe_xyz[3 * dst_g + 0] - atom_xyz[3 * src_g + 0] - dx;
        float vy = probe_xyz[3 * dst_g + 1] - atom_xyz[3 * src_g + 1] - dy;
        float vz = probe_xyz[3 * dst_g + 2] - atom_xyz[3 * src_g + 2] - dz;
        float r2 = fmaf(vx, vx, fmaf(vy, vy, vz * vz));
        float r = sqrtf(r2);
        float rinv = 1.0f / fmaxf(r, 1e-9f);
        float x = vx * rinv, y = vy * rinv, z = vz * rinv;
        float x2 = x * x, y2 = y * y, z2 = z * z;

        const float s3  = 1.7320508075688772f;
        const float s15 = 3.872983346207417f;
        float* S = s_sh + tid * 17;
        S[0]  = 1.f;
        S[1]  = s3 * x;
        S[2]  = s3 * y;
        S[3]  = s3 * z;
        S[4]  = s15 * x * y;
        S[5]  = s15 * y * z;
        S[6]  = 1.118033988749895f * (3.f * z2 - 1.f);
        S[7]  = s15 * x * z;
        S[8]  = 1.9364916731037085f * (x2 - y2);
        S[9]  = 2.091650066335189f * y * (3.f * x2 - y2);
        S[10] = 10.246950765959598f * x * y * z;
        S[11] = 1.6201851746019651f * y * (5.f * z2 - 1.f);
        S[12] = 1.3228756555322954f * (5.f * z2 * z - 3.f * z);
        S[13] = 1.6201851746019651f * x * (5.f * z2 - 1.f);
        S[14] = 5.123475382979799f * z * (x2 - y2);
        S[15] = 2.091650066335189f * x * (x2 - 3.f * y2);

        float f = r * ((float)(TN - 1) / RMAXF);
        f = fminf(f, (float)(TN - 1));
        int i0 = (int)f;
        i0 = min(i0, TN - 2);
        bool drop = (i0 >= ICUT);   // g(r>6) ~ 0: contribution negligible
        if (drop) i0 = TN - 2;      // clamp -> dropped reads hit one hot line
        s_i0[tid] = i0;
        s_w[tid] = f - (float)i0;
        s_src[tid] = src_g;
        s_dst[tid] = drop ? -1 : dst_g;
    } else {
        float* S = s_sh + tid * 17;
#pragma unroll
        for (int m = 0; m < 16; m++) S[m] = 0.f;
        s_i0[tid] = TN - 2;
        s_w[tid] = 0.f;
        s_src[tid] = 0;
        s_dst[tid] = -1;
    }
    __syncthreads();

    // half-warp per edge: one lerp-pair load per t + 16-lane reduce
    {
        int lane = tid & 31;
        int m = lane & 15;
        int hw = (tid >> 5) * 2 + (lane >> 4);
#pragma unroll 2
        for (int k = 0; k < 16; k++) {
            int el = hw * 16 + k;
            int i0 = s_i0[el];
            float w = s_w[el];
            float shm = s_sh[el * 17 + m];
            const __half2* G = g16 + i0 * 48 + m;
#pragma unroll
            for (int t = 0; t < 3; t++) {
                float2 gpair = __half22float2(__ldg(G + t * 16));
                float v = shm * fmaf(w, gpair.y - gpair.x, gpair.x);
                v += __shfl_xor_sync(0xFFFFFFFFu, v, 1);
                v += __shfl_xor_sync(0xFFFFFFFFu, v, 2);
                v += __shfl_xor_sync(0xFFFFFFFFu, v, 4);
                v += __shfl_xor_sync(0xFFFFFFFFu, v, 8);
                if (m == 0) s_sc[el * 4 + t] = v;
            }
        }
    }
    __syncthreads();

    // linked-list insert, contributing edges only
    if (e < E && s_dst[tid] >= 0) {
        rec[e] = make_float4(s_sc[tid * 4 + 0], s_sc[tid * 4 + 1],
                             s_sc[tid * 4 + 2], __int_as_float(s_src[tid]));
        nxt[e] = atomicExch(&head[s_dst[tid]], e);
    }
}

// ---------------- 5: prep — rep16 convert + rw dot --------------------------
__global__ void prep_rep_kernel(const float* __restrict__ atom_rep,
                                const float* __restrict__ w_out, int rows)
{
    int g = blockIdx.x * blockDim.x + threadIdx.x;
    int row = g >> 5;
    int lane = g & 31;
    if (row >= rows) return;
    float4 a = __ldg((const float4*)atom_rep + (size_t)row * 32 + lane);
    __half2 h0 = __floats2half2_rn(a.x, a.y);
    __half2 h1 = __floats2half2_rn(a.z, a.w);
    uint2 u;
    u.x = *(unsigned*)&h0;
    u.y = *(unsigned*)&h1;
    ((uint2*)rep16)[(size_t)row * 32 + lane] = u;
    float4 wv = __ldg((const float4*)w_out + lane);
    float s = fmaf(a.x, wv.x, fmaf(a.y, wv.y, fmaf(a.z, wv.z, a.w * wv.w)));
#pragma unroll
    for (int off = 16; off > 0; off >>= 1)
        s += __shfl_xor_sync(0xFFFFFFFFu, s, off);
    if (lane == 0) rw_table[row] = s;
}

// ---------------- 6: phase B — warp per probe, write once -------------------
__global__ void __launch_bounds__(256) phaseB_kernel(
    float* __restrict__ probes, float* __restrict__ out, int P, int AB)
{
    int g = blockIdx.x * blockDim.x + threadIdx.x;
    int p = g >> 5;
    int lane = g & 31;
    if (p >= P) return;

    float4 acc = make_float4(0.f, 0.f, 0.f, 0.f);
    float ov = 0.f;
    size_t repT2 = (size_t)AB * 64;
    const __half2* rep2 = (const __half2*)rep16;

    int e = head[p];
    while (e >= 0) {
        float4 c = __ldg(&rec[e]);           // broadcast (same addr all lanes)
        int src = __float_as_int(c.w);
        const __half2* p0 = rep2 + (size_t)src * 64 + lane * 2;
        uint2 u0 = __ldg((const uint2*)p0);
        uint2 u1 = __ldg((const uint2*)(p0 + repT2));
        uint2 u2 = __ldg((const uint2*)(p0 + 2 * repT2));
        float2 a0 = __half22float2(*(__half2*)&u0.x);
        float2 b0 = __half22float2(*(__half2*)&u0.y);
        float2 a1 = __half22float2(*(__half2*)&u1.x);
        float2 b1 = __half22float2(*(__half2*)&u1.y);
        float2 a2 = __half22float2(*(__half2*)&u2.x);
        float2 b2 = __half22float2(*(__half2*)&u2.y);
        acc.x += fmaf(c.x, a0.x, fmaf(c.y, a1.x, c.z * a2.x));
        acc.y += fmaf(c.x, a0.y, fmaf(c.y, a1.y, c.z * a2.y));
        acc.z += fmaf(c.x, b0.x, fmaf(c.y, b1.x, c.z * b2.x));
        acc.w += fmaf(c.x, b0.y, fmaf(c.y, b1.y, c.z * b2.y));
        if (lane == 0)
            ov += fmaf(c.x, rw_table[src],
                  fmaf(c.y, rw_table[AB + src], c.z * rw_table[2 * AB + src]));
        e = __ldg(&nxt[e]);
    }
    ((float4*)(probes + (size_t)p * 128))[lane] = acc;
    if (lane == 0) out[p] = ov;
}

extern "C" void kernel_launch(void* const* d_in, const int* in_sizes, int n_in,
                              void* d_out, int out_size)
{
    const float* atom_xyz  = (const float*)d_in[0];
    const float* probe_xyz = (const float*)d_in[1];
    const int*   edges     = (const int*)d_in[2];
    const float* ped       = (const float*)d_in[3];
    const float* cell      = (const float*)d_in[4];
    const float* atom_rep  = (const float*)d_in[8];
    const float* w1        = (const float*)d_in[9];
    const float* w2        = (const float*)d_in[10];
    const float* w_out     = (const float*)d_in[11];

    int B         = in_sizes[4] / 9;
    int n_atoms   = in_sizes[0] / (3 * B);
    int n_probes  = in_sizes[1] / (3 * B);
    int n_edges_b = in_sizes[2] / (2 * B);
    int E  = B * n_edges_b;
    int AB = B * n_atoms;
    int P  = B * n_probes;

    float* out    = (float*)d_out;      // first P: (B,P) potential
    float* probes = out + P;            // next P*128: probe features

    int actN = (TN * 300 > P) ? TN * 300 : P;
    rb_kernel<<<(TN * 10 + 255) / 256, 256>>>();
    act_kernel<<<(actN + 255) / 256, 256>>>(w1, P);       // + head init
    gtab16_kernel<<<(TN * 48 + 255) / 256, 256>>>(w2);
    phaseA_kernel<<<(E + 255) / 256, 256>>>(atom_xyz, probe_xyz, edges, ped,
                                            cell, E, n_edges_b, n_atoms,
                                            n_probes);     // 4th: profiled
    prep_rep_kernel<<<(3 * AB * 32 + 255) / 256, 256>>>(atom_rep, w_out, 3 * AB);
    phaseB_kernel<<<(P * 32 + 255) / 256, 256>>>(probes, out, P, AB);
}

// round 11
// speedup vs baseline: 2.5790x; 1.3336x over previous
#include <cuda_runtime.h>
#include <cuda_fp16.h>

#define TN 2048
#define RMAXF 8.0f
#define ICUT 1535            /* table index at r=6.0; g beyond is ~1e-8 */
#define MAXAB 32768
#define MAXE  640000
#define MAXP  262144

// Radial table (fp16 lerp pairs): g16[i*48+o] = (g[i][o], g[i+1][o]),
// g[i][t*16+m] = (silu(rb(r_i)@w1[t]) @ w2[t])[m] / sqrt(20).
// g(r)==~0 for r > 5.8, so dropping r>6 edges and clamping r>RMAXF is safe.
__device__ __align__(16) __half2 g16[TN * 48];
__device__ float rb_tab[TN * 10];
__device__ float act_tab[TN * 300];
__device__ float rw_table[3 * MAXAB];   // dot(atom_rep[t][a], w_out)
__device__ __half rep16[3 * MAXAB * 128];
// per-probe linked list of contributing edges
__device__ float4 rec[MAXE];            // (c0,c1,c2, src-as-float)
__device__ int    nxt[MAXE];
__device__ int    head[MAXP];

// ---------------- 1: radial basis table -------------------------------------
__global__ void rb_kernel()
{
    int id = blockIdx.x * blockDim.x + threadIdx.x;
    if (id >= TN * 10) return;
    int i = id / 10, k = id % 10;
    float r = (float)i * (RMAXF / (float)(TN - 1));
    const float step = 4.0f / 9.0f;
    float d = (r - (float)k * step) / step;
    rb_tab[id] = expf(-d * d) * 1.12f;
}

// ---------------- 2: hidden activations + head init -------------------------
__global__ void act_kernel(const float* __restrict__ w1, int P)
{
    int id = blockIdx.x * blockDim.x + threadIdx.x;
    if (id < P) head[id] = -1;
    if (id >= TN * 300) return;
    int i = id / 300, rem = id % 300;
    int t = rem / 100, j = rem % 100;
    const float* RB = rb_tab + i * 10;
    const float* W1 = w1 + t * 1000 + j;
    float a = 0.f;
#pragma unroll
    for (int k = 0; k < 10; k++)
        a = fmaf(__ldg(RB + k), __ldg(W1 + k * 100), a);
    act_tab[id] = a / (1.f + expf(-a));
}

// ---------------- 3: output table, fp16 lerp pairs directly -----------------
__global__ void gtab16_kernel(const float* __restrict__ w2)
{
    int id = blockIdx.x * blockDim.x + threadIdx.x;
    if (id >= TN * 48) return;
    int i = id / 48, o = id % 48;
    int t = o >> 4, m = o & 15;
    const float* A0 = act_tab + i * 300 + t * 100;
    const float* A1 = act_tab + min(i + 1, TN - 1) * 300 + t * 100;
    const float* W = w2 + t * 1600 + m;
    float h0 = 0.f, h1 = 0.f;
#pragma unroll 4
    for (int j = 0; j < 100; j++) {
        float wv = __ldg(W + j * 16);
        h0 = fmaf(__ldg(A0 + j), wv, h0);
        h1 = fmaf(__ldg(A1 + j), wv, h1);
    }
    const float scale = 0.22360679774997896f;  // 1/sqrt(20)
    g16[id] = __floats2half2_rn(h0 * scale, h1 * scale);
}

// ---------------- 4: phase A — thread per edge, survivors only --------------
__global__ void __launch_bounds__(256) phaseA_kernel(
    const float* __restrict__ atom_xyz,
    const float* __restrict__ probe_xyz,
    const int*   __restrict__ edges,
    const float* __restrict__ ped,
    const float* __restrict__ cell,
    int E, int n_edges_b, int n_atoms, int n_probes)
{
    int e = blockIdx.x * 256 + threadIdx.x;
    if (e >= E) return;

    int b = e / n_edges_b;
    int2 se = ((const int2*)edges)[e];
    int src_g = b * n_atoms + se.x;
    int dst_g = b * n_probes + se.y;
    float px = ped[3 * e], py = ped[3 * e + 1], pz = ped[3 * e + 2];
    const float* C = cell + b * 9;
    float dx = fmaf(px, __ldg(C + 0), fmaf(py, __ldg(C + 3), pz * __ldg(C + 6)));
    float dy = fmaf(px, __ldg(C + 1), fmaf(py, __ldg(C + 4), pz * __ldg(C + 7)));
    float dz = fmaf(px, __ldg(C + 2), fmaf(py, __ldg(C + 5), pz * __ldg(C + 8)));
    float vx = probe_xyz[3 * dst_g + 0] - atom_xyz[3 * src_g + 0] - dx;
    float vy = probe_xyz[3 * dst_g + 1] - atom_xyz[3 * src_g + 1] - dy;
    float vz = probe_xyz[3 * dst_g + 2] - atom_xyz[3 * src_g + 2] - dz;
    float r2 = fmaf(vx, vx, fmaf(vy, vy, vz * vz));
    float r = sqrtf(r2);

    float f = r * ((float)(TN - 1) / RMAXF);
    int i0 = (int)f;
    if (i0 >= ICUT) return;          // g(r>6) ~ 0: drop, no further work

    float w = f - (float)i0;
    float rinv = 1.0f / fmaxf(r, 1e-9f);
    float x = vx * rinv, y = vy * rinv, z = vz * rinv;
    float x2 = x * x, y2 = y * y, z2 = z * z;

    const float s3  = 1.7320508075688772f;
    const float s15 = 3.872983346207417f;
    float sh[16];
    sh[0]  = 1.f;
    sh[1]  = s3 * x;
    sh[2]  = s3 * y;
    sh[3]  = s3 * z;
    sh[4]  = s15 * x * y;
    sh[5]  = s15 * y * z;
    sh[6]  = 1.118033988749895f * (3.f * z2 - 1.f);
    sh[7]  = s15 * x * z;
    sh[8]  = 1.9364916731037085f * (x2 - y2);
    sh[9]  = 2.091650066335189f * y * (3.f * x2 - y2);
    sh[10] = 10.246950765959598f * x * y * z;
    sh[11] = 1.6201851746019651f * y * (5.f * z2 - 1.f);
    sh[12] = 1.3228756555322954f * (5.f * z2 * z - 3.f * z);
    sh[13] = 1.6201851746019651f * x * (5.f * z2 - 1.f);
    sh[14] = 5.123475382979799f * z * (x2 - y2);
    sh[15] = 2.091650066335189f * x * (x2 - 3.f * y2);

    // table read: 12 aligned 16B loads (192 B contiguous per entry)
    const uint4* G = (const uint4*)(g16 + (size_t)i0 * 48);
    float sc[3];
#pragma unroll
    for (int t = 0; t < 3; t++) {
        float acc = 0.f;
#pragma unroll
        for (int q = 0; q < 4; q++) {
            uint4 u = __ldg(G + t * 4 + q);
            float2 p0 = __half22float2(*(__half2*)&u.x);
            float2 p1 = __half22float2(*(__half2*)&u.y);
            float2 p2 = __half22float2(*(__half2*)&u.z);
            float2 p3 = __half22float2(*(__half2*)&u.w);
            int mb = q * 4;
            acc = fmaf(sh[mb + 0], fmaf(w, p0.y - p0.x, p0.x), acc);
            acc = fmaf(sh[mb + 1], fmaf(w, p1.y - p1.x, p1.x), acc);
            acc = fmaf(sh[mb + 2], fmaf(w, p2.y - p2.x, p2.x), acc);
            acc = fmaf(sh[mb + 3], fmaf(w, p3.y - p3.x, p3.x), acc);
        }
        sc[t] = acc;
    }

    rec[e] = make_float4(sc[0], sc[1], sc[2], __int_as_float(src_g));
    nxt[e] = atomicExch(&head[dst_g], e);
}

// ---------------- 5: prep — rep16 convert + rw dot --------------------------
__global__ void prep_rep_kernel(const float* __restrict__ atom_rep,
                                const float* __restrict__ w_out, int rows)
{
    int g = blockIdx.x * blockDim.x + threadIdx.x;
    int row = g >> 5;
    int lane = g & 31;
    if (row >= rows) return;
    float4 a = __ldg((const float4*)atom_rep + (size_t)row * 32 + lane);
    __half2 h0 = __floats2half2_rn(a.x, a.y);
    __half2 h1 = __floats2half2_rn(a.z, a.w);
    uint2 u;
    u.x = *(unsigned*)&h0;
    u.y = *(unsigned*)&h1;
    ((uint2*)rep16)[(size_t)row * 32 + lane] = u;
    float4 wv = __ldg((const float4*)w_out + lane);
    float s = fmaf(a.x, wv.x, fmaf(a.y, wv.y, fmaf(a.z, wv.z, a.w * wv.w)));
#pragma unroll
    for (int off = 16; off > 0; off >>= 1)
        s += __shfl_xor_sync(0xFFFFFFFFu, s, off);
    if (lane == 0) rw_table[row] = s;
}

// ---------------- 6: phase B — warp per probe, write once -------------------
__global__ void __launch_bounds__(256) phaseB_kernel(
    float* __restrict__ probes, float* __restrict__ out, int P, int AB)
{
    int g = blockIdx.x * blockDim.x + threadIdx.x;
    int p = g >> 5;
    int lane = g & 31;
    if (p >= P) return;

    float4 acc = make_float4(0.f, 0.f, 0.f, 0.f);
    float ov = 0.f;
    size_t repT2 = (size_t)AB * 64;
    const __half2* rep2 = (const __half2*)rep16;

    int e = head[p];
    while (e >= 0) {
        float4 c = __ldg(&rec[e]);           // broadcast (same addr all lanes)
        int src = __float_as_int(c.w);
        const __half2* p0 = rep2 + (size_t)src * 64 + lane * 2;
        uint2 u0 = __ldg((const uint2*)p0);
        uint2 u1 = __ldg((const uint2*)(p0 + repT2));
        uint2 u2 = __ldg((const uint2*)(p0 + 2 * repT2));
        float2 a0 = __half22float2(*(__half2*)&u0.x);
        float2 b0 = __half22float2(*(__half2*)&u0.y);
        float2 a1 = __half22float2(*(__half2*)&u1.x);
        float2 b1 = __half22float2(*(__half2*)&u1.y);
        float2 a2 = __half22float2(*(__half2*)&u2.x);
        float2 b2 = __half22float2(*(__half2*)&u2.y);
        acc.x += fmaf(c.x, a0.x, fmaf(c.y, a1.x, c.z * a2.x));
        acc.y += fmaf(c.x, a0.y, fmaf(c.y, a1.y, c.z * a2.y));
        acc.z += fmaf(c.x, b0.x, fmaf(c.y, b1.x, c.z * b2.x));
        acc.w += fmaf(c.x, b0.y, fmaf(c.y, b1.y, c.z * b2.y));
        if (lane == 0)
            ov += fmaf(c.x, rw_table[src],
                  fmaf(c.y, rw_table[AB + src], c.z * rw_table[2 * AB + src]));
        e = __ldg(&nxt[e]);
    }
    ((float4*)(probes + (size_t)p * 128))[lane] = acc;
    if (lane == 0) out[p] = ov;
}

extern "C" void kernel_launch(void* const* d_in, const int* in_sizes, int n_in,
                              void* d_out, int out_size)
{
    const float* atom_xyz  = (const float*)d_in[0];
    const float* probe_xyz = (const float*)d_in[1];
    const int*   edges     = (const int*)d_in[2];
    const float* ped       = (const float*)d_in[3];
    const float* cell      = (const float*)d_in[4];
    const float* atom_rep  = (const float*)d_in[8];
    const float* w1        = (const float*)d_in[9];
    const float* w2        = (const float*)d_in[10];
    const float* w_out     = (const float*)d_in[11];

    int B         = in_sizes[4] / 9;
    int n_atoms   = in_sizes[0] / (3 * B);
    int n_probes  = in_sizes[1] / (3 * B);
    int n_edges_b = in_sizes[2] / (2 * B);
    int E  = B * n_edges_b;
    int AB = B * n_atoms;
    int P  = B * n_probes;

    float* out    = (float*)d_out;      // first P: (B,P) potential
    float* probes = out + P;            // next P*128: probe features

    int actN = (TN * 300 > P) ? TN * 300 : P;
    rb_kernel<<<(TN * 10 + 255) / 256, 256>>>();
    act_kernel<<<(actN + 255) / 256, 256>>>(w1, P);       // + head init
    gtab16_kernel<<<(TN * 48 + 255) / 256, 256>>>(w2);
    phaseA_kernel<<<(E + 255) / 256, 256>>>(atom_xyz, probe_xyz, edges, ped,
                                            cell, E, n_edges_b, n_atoms,
                                            n_probes);     // 4th: profiled
    prep_rep_kernel<<<(3 * AB * 32 + 255) / 256, 256>>>(atom_rep, w_out, 3 * AB);
    phaseB_kernel<<<(P * 32 + 255) / 256, 256>>>(probes, out, P, AB);
}